// round 5
// baseline (speedup 1.0000x reference)
#include <cuda_runtime.h>

#define NN 100000
#define NE 1600000
#define D  128
#define DOUT 40
#define ROWS 8
#define NGROUP (NN / ROWS)

#define SCAN_B 512
#define NSCANB ((NN + SCAN_B - 1) / SCAN_B)   // 196

#define XS_STRIDE 132
#define TILE 128
#define NTILE ((NN + TILE - 1) / TILE)        // 782

// Scratch (allocation-free rule: __device__ globals)
__device__ float g_bufA[(size_t)NN * D];   // t_s = (x@W)*dinv  (gather source)
__device__ float g_bufB[(size_t)NN * D];   // aggregated result
__device__ float g_dinv[NN];
__device__ int   g_cnt[NN];
__device__ int   g_rowptr[NN];
__device__ int   g_woff[NN];
__device__ int   g_srcs[NE];
__device__ int   g_bsum[NSCANB];
__device__ int   g_boff[NSCANB];

__device__ __forceinline__ unsigned long long ffma2(unsigned long long a,
                                                    unsigned long long b,
                                                    unsigned long long c) {
    unsigned long long d;
    asm("fma.rn.f32x2 %0, %1, %2, %3;" : "=l"(d) : "l"(a), "l"(b), "l"(c));
    return d;
}
__device__ __forceinline__ unsigned long long pack2(float lo, float hi) {
    unsigned long long d;
    asm("mov.b64 %0, {%1, %2};" : "=l"(d) : "f"(lo), "f"(hi));
    return d;
}
__device__ __forceinline__ float2 unpack2(unsigned long long v) {
    float2 r;
    asm("mov.b64 {%0, %1}, %2;" : "=f"(r.x), "=f"(r.y) : "l"(v));
    return r;
}

// ---------------- CSR build ----------------
__global__ void k_zero() {
    int i = blockIdx.x * blockDim.x + threadIdx.x;
    if (i < NN) g_cnt[i] = 0;
}
__global__ void k_hist(const int* __restrict__ dst) {
    int i = blockIdx.x * blockDim.x + threadIdx.x;
    if (i < NE) atomicAdd(&g_cnt[dst[i]], 1);
}
__global__ __launch_bounds__(SCAN_B)
void k_scan1() {
    __shared__ int sh[SCAN_B];
    int i = blockIdx.x * SCAN_B + threadIdx.x;
    int v = (i < NN) ? g_cnt[i] : 0;
    sh[threadIdx.x] = v;
    __syncthreads();
    int acc = v;
#pragma unroll
    for (int off = 1; off < SCAN_B; off <<= 1) {
        int t = (threadIdx.x >= off) ? sh[threadIdx.x - off] : 0;
        __syncthreads();
        acc += t;
        sh[threadIdx.x] = acc;
        __syncthreads();
    }
    if (i < NN) g_rowptr[i] = acc - v;
    if (threadIdx.x == SCAN_B - 1) g_bsum[blockIdx.x] = acc;
}
__global__ __launch_bounds__(256)
void k_scan2() {
    __shared__ int sh[256];
    int t = threadIdx.x;
    int v = (t < NSCANB) ? g_bsum[t] : 0;
    sh[t] = v;
    __syncthreads();
    int acc = v;
#pragma unroll
    for (int off = 1; off < 256; off <<= 1) {
        int u = (t >= off) ? sh[t - off] : 0;
        __syncthreads();
        acc += u;
        sh[t] = acc;
        __syncthreads();
    }
    if (t < NSCANB) g_boff[t] = acc - v;   // exclusive
}
__global__ void k_finalize() {
    int i = blockIdx.x * blockDim.x + threadIdx.x;
    if (i < NN) {
        int p = g_rowptr[i] + g_boff[i / SCAN_B];
        g_rowptr[i] = p;
        g_woff[i]   = p;
        g_dinv[i]   = rsqrtf((float)(g_cnt[i] + 1));
    }
}
__global__ void k_scatter(const int* __restrict__ src, const int* __restrict__ dst) {
    int i = blockIdx.x * blockDim.x + threadIdx.x;
    if (i < NE) {
        int pos = atomicAdd(&g_woff[dst[i]], 1);
        g_srcs[pos] = src[i];
    }
}

// ---------------- register-tiled GEMM: 128x128 block tile, 8x8 per thread ----------------
// MODE 0: X = raw input x.        t = x @ W;            write t*dinv -> bufA
// MODE 1: input = g_bufB (agg).   h = relu(dinv*agg+b); t = h @ W;  write t*dinv -> bufA
template <int MODE>
__global__ __launch_bounds__(256)
void k_gemm(const float* __restrict__ X, const float* __restrict__ W,
            const float* __restrict__ bias)
{
    extern __shared__ float sh[];
    float* Ws = sh;                 // D*D
    float* Xs = sh + D * D;         // D * XS_STRIDE, transposed: Xs[k*XS_STRIDE + row]

    const int tid = threadIdx.x;
    const int tile = blockIdx.x * TILE;

    // load W (row-major [k][j])
    for (int i = tid; i < D * D / 4; i += 256)
        ((float4*)Ws)[i] = ((const float4*)W)[i];

    // stage X tile transposed (+ fused MODE-1 prologue)
    for (int idx = tid; idx < TILE * (D / 4); idx += 256) {
        int row = idx & (TILE - 1);
        int c4  = idx >> 7;
        int grow = tile + row;
        float4 v = make_float4(0.f, 0.f, 0.f, 0.f);
        if (grow < NN) {
            if (MODE == 0) {
                v = ((const float4*)(X + (size_t)grow * D))[c4];
            } else {
                float di = g_dinv[grow];
                float4 a = ((const float4*)(g_bufB + (size_t)grow * D))[c4];
                float4 b = ((const float4*)bias)[c4];
                v.x = fmaxf(fmaf(di, a.x, b.x), 0.f);
                v.y = fmaxf(fmaf(di, a.y, b.y), 0.f);
                v.z = fmaxf(fmaf(di, a.z, b.z), 0.f);
                v.w = fmaxf(fmaf(di, a.w, b.w), 0.f);
            }
        }
        int k0 = c4 * 4;
        Xs[(k0 + 0) * XS_STRIDE + row] = v.x;
        Xs[(k0 + 1) * XS_STRIDE + row] = v.y;
        Xs[(k0 + 2) * XS_STRIDE + row] = v.z;
        Xs[(k0 + 3) * XS_STRIDE + row] = v.w;
    }
    __syncthreads();

    const int lane = tid & 31, warp = tid >> 5;
    const int wr = warp & 1, wc = warp >> 1;       // 2 x 4 warp grid
    const int rt = lane >> 2, ct = lane & 3;       // 8 x 4 threads
    const int rowb = wr * 64 + rt * 8;             // 8 rows per thread
    const int colb = wc * 32 + ct * 8;             // 8 cols per thread

    unsigned long long acc[8][4];
#pragma unroll
    for (int r = 0; r < 8; r++)
#pragma unroll
        for (int c = 0; c < 4; c++) acc[r][c] = 0ull;

#pragma unroll 8
    for (int k = 0; k < D; k++) {
        float4 xa = *(const float4*)(Xs + k * XS_STRIDE + rowb);
        float4 xb = *(const float4*)(Xs + k * XS_STRIDE + rowb + 4);
        ulonglong2 wA = *(const ulonglong2*)(Ws + k * D + colb);
        ulonglong2 wB = *(const ulonglong2*)(Ws + k * D + colb + 4);
        float xs[8] = {xa.x, xa.y, xa.z, xa.w, xb.x, xb.y, xb.z, xb.w};
#pragma unroll
        for (int r = 0; r < 8; r++) {
            unsigned long long xvv = pack2(xs[r], xs[r]);
            acc[r][0] = ffma2(xvv, wA.x, acc[r][0]);
            acc[r][1] = ffma2(xvv, wA.y, acc[r][1]);
            acc[r][2] = ffma2(xvv, wB.x, acc[r][2]);
            acc[r][3] = ffma2(xvv, wB.y, acc[r][3]);
        }
    }

    // epilogue: *dinv, store to bufA
#pragma unroll
    for (int r = 0; r < 8; r++) {
        int grow = tile + rowb + r;
        if (grow < NN) {
            float di = g_dinv[grow];
            float2 p0 = unpack2(acc[r][0]);
            float2 p1 = unpack2(acc[r][1]);
            float2 p2 = unpack2(acc[r][2]);
            float2 p3 = unpack2(acc[r][3]);
            float4 o0 = make_float4(p0.x * di, p0.y * di, p1.x * di, p1.y * di);
            float4 o1 = make_float4(p2.x * di, p2.y * di, p3.x * di, p3.y * di);
            float* base = g_bufA + (size_t)grow * D + colb;
            *(float4*)(base)     = o0;
            *(float4*)(base + 4) = o1;
        }
    }
}

// ---------------- CSR gather aggregation: warp per node ----------------
__global__ __launch_bounds__(256)
void k_gather()
{
    const int v = (blockIdx.x * blockDim.x + threadIdx.x) >> 5;
    if (v >= NN) return;
    const int lane = threadIdx.x & 31;
    const int start = g_rowptr[v];
    const int deg   = g_cnt[v];

    float4 acc = ((const float4*)(g_bufA + (size_t)v * D))[lane];  // self loop

    int j = 0;
    for (; j + 4 <= deg; j += 4) {
        int s0 = __ldg(g_srcs + start + j + 0);
        int s1 = __ldg(g_srcs + start + j + 1);
        int s2 = __ldg(g_srcs + start + j + 2);
        int s3 = __ldg(g_srcs + start + j + 3);
        float4 v0 = ((const float4*)(g_bufA + (size_t)s0 * D))[lane];
        float4 v1 = ((const float4*)(g_bufA + (size_t)s1 * D))[lane];
        float4 v2 = ((const float4*)(g_bufA + (size_t)s2 * D))[lane];
        float4 v3 = ((const float4*)(g_bufA + (size_t)s3 * D))[lane];
        acc.x += v0.x + v1.x + v2.x + v3.x;
        acc.y += v0.y + v1.y + v2.y + v3.y;
        acc.z += v0.z + v1.z + v2.z + v3.z;
        acc.w += v0.w + v1.w + v2.w + v3.w;
    }
    for (; j < deg; j++) {
        int s = __ldg(g_srcs + start + j);
        float4 u = ((const float4*)(g_bufA + (size_t)s * D))[lane];
        acc.x += u.x; acc.y += u.y; acc.z += u.z; acc.w += u.w;
    }
    ((float4*)(g_bufB + (size_t)v * D))[lane] = acc;
}

// ---------------- final: h2 = dinv*agg2 + b2; out = h2 @ Wout + bout ----------------
__global__ __launch_bounds__(256)
void k_out(const float* __restrict__ Wout, const float* __restrict__ b2,
           const float* __restrict__ bout, float* __restrict__ out)
{
    extern __shared__ float Ws[];          // D*DOUT floats
    const int tid = threadIdx.x;
    for (int i = tid; i < D * DOUT; i += blockDim.x)
        Ws[i] = Wout[i];
    __syncthreads();

    const int lane = tid & 31, warp = tid >> 5;
    const int NW = blockDim.x >> 5;
    const bool act = (lane < DOUT / 2);

    float4 b2r = ((const float4*)b2)[lane];
    float bo0 = 0.f, bo1 = 0.f;
    if (act) { bo0 = bout[2 * lane]; bo1 = bout[2 * lane + 1]; }

    for (int g = blockIdx.x * NW + warp; g < NGROUP; g += gridDim.x * NW) {
        const int row0 = g * ROWS;
        float xr[ROWS][4];
#pragma unroll
        for (int r = 0; r < ROWS; r++) {
            const int row = row0 + r;
            const float di = g_dinv[row];
            float4 a = ((const float4*)(g_bufB + (size_t)row * D))[lane];
            xr[r][0] = fmaf(di, a.x, b2r.x);
            xr[r][1] = fmaf(di, a.y, b2r.y);
            xr[r][2] = fmaf(di, a.z, b2r.z);
            xr[r][3] = fmaf(di, a.w, b2r.w);
        }

        unsigned long long acc[ROWS];
#pragma unroll
        for (int r = 0; r < ROWS; r++) acc[r] = 0ull;

#pragma unroll 4
        for (int k = 0; k < D; k++) {
            unsigned long long w = 0ull;
            if (act) w = *(const unsigned long long*)(Ws + k * DOUT + 2 * lane);
#pragma unroll
            for (int r = 0; r < ROWS; r++) {
                float xv = __shfl_sync(0xffffffffu, xr[r][k & 3], k >> 2);
                unsigned long long xvv = pack2(xv, xv);
                acc[r] = ffma2(xvv, w, acc[r]);
            }
        }

        if (act) {
#pragma unroll
            for (int r = 0; r < ROWS; r++) {
                float2 v = unpack2(acc[r]);
                float2 o = make_float2(v.x + bo0, v.y + bo1);
                *(float2*)(out + (size_t)(row0 + r) * DOUT + 2 * lane) = o;
            }
        }
    }
}

extern "C" void kernel_launch(void* const* d_in, const int* in_sizes, int n_in,
                              void* d_out, int out_size)
{
    const float* x    = (const float*)d_in[0];
    const int*   ei   = (const int*)  d_in[1];
    const float* W1   = (const float*)d_in[2];
    const float* b1   = (const float*)d_in[3];
    const float* W2   = (const float*)d_in[4];
    const float* b2   = (const float*)d_in[5];
    const float* Wout = (const float*)d_in[6];
    const float* bout = (const float*)d_in[7];
    const int* src = ei;
    const int* dst = ei + NE;
    float* out = (float*)d_out;

    const int SMEM_GEMM = (D * D + D * XS_STRIDE) * 4;   // ~132 KB
    const int SMEM_OUT  = D * DOUT * 4;

    cudaFuncSetAttribute(k_gemm<0>, cudaFuncAttributeMaxDynamicSharedMemorySize, SMEM_GEMM);
    cudaFuncSetAttribute(k_gemm<1>, cudaFuncAttributeMaxDynamicSharedMemorySize, SMEM_GEMM);

    const int GATHER_GRID = (NN * 32 + 255) / 256;
    const int OUT_GRID = (NGROUP + 7) / 8;

    // ---- CSR build ----
    k_zero<<<(NN + 255) / 256, 256>>>();
    k_hist<<<(NE + 255) / 256, 256>>>(dst);
    k_scan1<<<NSCANB, SCAN_B>>>();
    k_scan2<<<1, 256>>>();
    k_finalize<<<(NN + 255) / 256, 256>>>();
    k_scatter<<<(NE + 255) / 256, 256>>>(src, dst);

    // ---- layer 1 ----
    k_gemm<0><<<NTILE, 256, SMEM_GEMM>>>(x, W1, nullptr);
    k_gather<<<GATHER_GRID, 256>>>();

    // ---- layer 2 ----
    k_gemm<1><<<NTILE, 256, SMEM_GEMM>>>(nullptr, W2, b1);
    k_gather<<<GATHER_GRID, 256>>>();

    // ---- output layer ----
    k_out<<<OUT_GRID, 256, SMEM_OUT>>>(Wout, b2, bout, out);
}

// round 6
// speedup vs baseline: 1.5553x; 1.5553x over previous
#include <cuda_runtime.h>

#define NN 100000
#define NE 1600000
#define D  128
#define DOUT 40
#define ROWS 8
#define NGROUP (NN / ROWS)

#define SCAN_B 512
#define NSCANB ((NN + SCAN_B - 1) / SCAN_B)   // 196

// Scratch (allocation-free rule: __device__ globals)
__device__ float g_bufA[(size_t)NN * D];    // t_s = (x@W1)*dinv  (gather source)
__device__ float g_bufB[(size_t)NN * D];    // layer-1 aggregated result
__device__ float g_bufU[(size_t)NN * DOUT]; // u_s = dinv*(h1@W2') (gather source, 40-dim)
__device__ float g_dinv[NN];
__device__ int   g_cnt[NN];
__device__ int   g_rowptr[NN];
__device__ int   g_woff[NN];
__device__ int   g_srcs[NE];
__device__ int   g_bsum[NSCANB];
__device__ int   g_boff[NSCANB];
__device__ float g_W2p[D * DOUT];           // W2 @ Wout
__device__ float g_c[DOUT];                 // b2 @ Wout + bout

__device__ __forceinline__ unsigned long long ffma2(unsigned long long a,
                                                    unsigned long long b,
                                                    unsigned long long c) {
    unsigned long long d;
    asm("fma.rn.f32x2 %0, %1, %2, %3;" : "=l"(d) : "l"(a), "l"(b), "l"(c));
    return d;
}
__device__ __forceinline__ unsigned long long pack2(float lo, float hi) {
    unsigned long long d;
    asm("mov.b64 %0, {%1, %2};" : "=l"(d) : "f"(lo), "f"(hi));
    return d;
}
__device__ __forceinline__ float2 unpack2(unsigned long long v) {
    float2 r;
    asm("mov.b64 {%0, %1}, %2;" : "=f"(r.x), "=f"(r.y) : "l"(v));
    return r;
}

// ---------------- CSR build ----------------
__global__ void k_zero() {
    int i = blockIdx.x * blockDim.x + threadIdx.x;
    if (i < NN) g_cnt[i] = 0;
}
__global__ void k_hist(const int* __restrict__ dst) {
    int i = blockIdx.x * blockDim.x + threadIdx.x;
    if (i < NE) atomicAdd(&g_cnt[dst[i]], 1);
}
__global__ __launch_bounds__(SCAN_B)
void k_scan1() {
    __shared__ int sh[SCAN_B];
    int i = blockIdx.x * SCAN_B + threadIdx.x;
    int v = (i < NN) ? g_cnt[i] : 0;
    sh[threadIdx.x] = v;
    __syncthreads();
    int acc = v;
#pragma unroll
    for (int off = 1; off < SCAN_B; off <<= 1) {
        int t = (threadIdx.x >= off) ? sh[threadIdx.x - off] : 0;
        __syncthreads();
        acc += t;
        sh[threadIdx.x] = acc;
        __syncthreads();
    }
    if (i < NN) g_rowptr[i] = acc - v;
    if (threadIdx.x == SCAN_B - 1) g_bsum[blockIdx.x] = acc;
}
__global__ __launch_bounds__(256)
void k_scan2() {
    __shared__ int sh[256];
    int t = threadIdx.x;
    int v = (t < NSCANB) ? g_bsum[t] : 0;
    sh[t] = v;
    __syncthreads();
    int acc = v;
#pragma unroll
    for (int off = 1; off < 256; off <<= 1) {
        int u = (t >= off) ? sh[t - off] : 0;
        __syncthreads();
        acc += u;
        sh[t] = acc;
        __syncthreads();
    }
    if (t < NSCANB) g_boff[t] = acc - v;   // exclusive
}
__global__ void k_finalize() {
    int i = blockIdx.x * blockDim.x + threadIdx.x;
    if (i < NN) {
        int p = g_rowptr[i] + g_boff[i / SCAN_B];
        g_rowptr[i] = p;
        g_woff[i]   = p;
        g_dinv[i]   = rsqrtf((float)(g_cnt[i] + 1));
    }
}
__global__ void k_scatter(const int* __restrict__ src, const int* __restrict__ dst) {
    int i = blockIdx.x * blockDim.x + threadIdx.x;
    if (i < NE) {
        int pos = atomicAdd(&g_woff[dst[i]], 1);
        g_srcs[pos] = src[i];
    }
}

// ---------------- weight folding: W2' = W2 @ Wout ; c = b2 @ Wout + bout ----------------
__global__ void k_fold(const float* __restrict__ W2, const float* __restrict__ Wout,
                       const float* __restrict__ b2, const float* __restrict__ bout)
{
    int t = blockIdx.x * blockDim.x + threadIdx.x;
    if (t < D * DOUT) {
        int k = t / DOUT, j = t % DOUT;
        float s = 0.f;
#pragma unroll 8
        for (int m = 0; m < D; m++)
            s = fmaf(W2[k * D + m], Wout[m * DOUT + j], s);
        g_W2p[t] = s;
    } else if (t < D * DOUT + DOUT) {
        int j = t - D * DOUT;
        float s = bout[j];
#pragma unroll 8
        for (int m = 0; m < D; m++)
            s = fmaf(b2[m], Wout[m * DOUT + j], s);
        g_c[j] = s;
    }
}

// ---------------- GEMM1 (8 rows per warp, FFMA2, W in smem) ----------------
// t = x @ W1; write t*dinv -> bufA
__global__ __launch_bounds__(256)
void k_gemm(const float* __restrict__ X, const float* __restrict__ W)
{
    extern __shared__ float Ws[];          // D*D floats
    const int tid = threadIdx.x;
    for (int i = tid; i < D * D / 4; i += blockDim.x)
        ((float4*)Ws)[i] = ((const float4*)W)[i];
    __syncthreads();

    const int lane = tid & 31, warp = tid >> 5;
    const int NW = blockDim.x >> 5;

    for (int g = blockIdx.x * NW + warp; g < NGROUP; g += gridDim.x * NW) {
        const int row0 = g * ROWS;
        float xr[ROWS][4];
        float di[ROWS];
#pragma unroll
        for (int r = 0; r < ROWS; r++) {
            const int row = row0 + r;
            di[r] = g_dinv[row];
            float4 v = ((const float4*)(X + (size_t)row * D))[lane];
            xr[r][0] = v.x; xr[r][1] = v.y; xr[r][2] = v.z; xr[r][3] = v.w;
        }

        unsigned long long acc0[ROWS], acc1[ROWS];
#pragma unroll
        for (int r = 0; r < ROWS; r++) { acc0[r] = 0ull; acc1[r] = 0ull; }

#pragma unroll 4
        for (int k = 0; k < D; k++) {
            ulonglong2 w = ((const ulonglong2*)Ws)[k * 32 + lane];
#pragma unroll
            for (int r = 0; r < ROWS; r++) {
                float xv = __shfl_sync(0xffffffffu, xr[r][k & 3], k >> 2);
                unsigned long long xvv = pack2(xv, xv);
                acc0[r] = ffma2(xvv, w.x, acc0[r]);
                acc1[r] = ffma2(xvv, w.y, acc1[r]);
            }
        }

#pragma unroll
        for (int r = 0; r < ROWS; r++) {
            const int row = row0 + r;
            float2 lo = unpack2(acc0[r]);
            float2 hi = unpack2(acc1[r]);
            float4 o = make_float4(lo.x * di[r], lo.y * di[r],
                                   hi.x * di[r], hi.y * di[r]);
            ((float4*)(g_bufA + (size_t)row * D))[lane] = o;
        }
    }
}

// ---------------- CSR gather (128-dim): warp per node ----------------
__global__ __launch_bounds__(256)
void k_gather()
{
    const int v = (blockIdx.x * blockDim.x + threadIdx.x) >> 5;
    if (v >= NN) return;
    const int lane = threadIdx.x & 31;
    const int start = g_rowptr[v];
    const int deg   = g_cnt[v];

    float4 acc = ((const float4*)(g_bufA + (size_t)v * D))[lane];  // self loop

    int j = 0;
    for (; j + 4 <= deg; j += 4) {
        int s0 = __ldg(g_srcs + start + j + 0);
        int s1 = __ldg(g_srcs + start + j + 1);
        int s2 = __ldg(g_srcs + start + j + 2);
        int s3 = __ldg(g_srcs + start + j + 3);
        float4 v0 = ((const float4*)(g_bufA + (size_t)s0 * D))[lane];
        float4 v1 = ((const float4*)(g_bufA + (size_t)s1 * D))[lane];
        float4 v2 = ((const float4*)(g_bufA + (size_t)s2 * D))[lane];
        float4 v3 = ((const float4*)(g_bufA + (size_t)s3 * D))[lane];
        acc.x += v0.x + v1.x + v2.x + v3.x;
        acc.y += v0.y + v1.y + v2.y + v3.y;
        acc.z += v0.z + v1.z + v2.z + v3.z;
        acc.w += v0.w + v1.w + v2.w + v3.w;
    }
    for (; j < deg; j++) {
        int s = __ldg(g_srcs + start + j);
        float4 u = ((const float4*)(g_bufA + (size_t)s * D))[lane];
        acc.x += u.x; acc.y += u.y; acc.z += u.z; acc.w += u.w;
    }
    ((float4*)(g_bufB + (size_t)v * D))[lane] = acc;
}

// ---------------- small GEMM: u = [relu(dinv*agg1 + b1) @ W2'] * dinv -> bufU ----------------
__global__ __launch_bounds__(256)
void k_small(const float* __restrict__ b1)
{
    extern __shared__ float Ws[];          // D*DOUT floats
    const int tid = threadIdx.x;
    for (int i = tid; i < D * DOUT; i += blockDim.x)
        Ws[i] = g_W2p[i];
    __syncthreads();

    const int lane = tid & 31, warp = tid >> 5;
    const int NW = blockDim.x >> 5;
    const bool act = (lane < DOUT / 2);

    float4 b1r = ((const float4*)b1)[lane];

    for (int g = blockIdx.x * NW + warp; g < NGROUP; g += gridDim.x * NW) {
        const int row0 = g * ROWS;
        float xr[ROWS][4];
        float di[ROWS];
#pragma unroll
        for (int r = 0; r < ROWS; r++) {
            const int row = row0 + r;
            di[r] = g_dinv[row];
            float4 a = ((const float4*)(g_bufB + (size_t)row * D))[lane];
            xr[r][0] = fmaxf(fmaf(di[r], a.x, b1r.x), 0.f);
            xr[r][1] = fmaxf(fmaf(di[r], a.y, b1r.y), 0.f);
            xr[r][2] = fmaxf(fmaf(di[r], a.z, b1r.z), 0.f);
            xr[r][3] = fmaxf(fmaf(di[r], a.w, b1r.w), 0.f);
        }

        unsigned long long acc[ROWS];
#pragma unroll
        for (int r = 0; r < ROWS; r++) acc[r] = 0ull;

#pragma unroll 4
        for (int k = 0; k < D; k++) {
            unsigned long long w = 0ull;
            if (act) w = *(const unsigned long long*)(Ws + k * DOUT + 2 * lane);
#pragma unroll
            for (int r = 0; r < ROWS; r++) {
                float xv = __shfl_sync(0xffffffffu, xr[r][k & 3], k >> 2);
                unsigned long long xvv = pack2(xv, xv);
                acc[r] = ffma2(xvv, w, acc[r]);
            }
        }

        if (act) {
#pragma unroll
            for (int r = 0; r < ROWS; r++) {
                float2 v = unpack2(acc[r]);
                float2 o = make_float2(v.x * di[r], v.y * di[r]);
                *(float2*)(g_bufU + (size_t)(row0 + r) * DOUT + 2 * lane) = o;
            }
        }
    }
}

// ---------------- CSR gather (40-dim) + final epilogue: out = dinv*acc + c ----------------
__global__ __launch_bounds__(256)
void k_gather2(float* __restrict__ out)
{
    const int v = (blockIdx.x * blockDim.x + threadIdx.x) >> 5;
    if (v >= NN) return;
    const int lane = threadIdx.x & 31;
    if (lane >= DOUT / 2) return;
    const int start = g_rowptr[v];
    const int deg   = g_cnt[v];
    const float di  = g_dinv[v];

    float2 acc = *(const float2*)(g_bufU + (size_t)v * DOUT + 2 * lane);  // self

    int j = 0;
    for (; j + 4 <= deg; j += 4) {
        int s0 = __ldg(g_srcs + start + j + 0);
        int s1 = __ldg(g_srcs + start + j + 1);
        int s2 = __ldg(g_srcs + start + j + 2);
        int s3 = __ldg(g_srcs + start + j + 3);
        float2 v0 = *(const float2*)(g_bufU + (size_t)s0 * DOUT + 2 * lane);
        float2 v1 = *(const float2*)(g_bufU + (size_t)s1 * DOUT + 2 * lane);
        float2 v2 = *(const float2*)(g_bufU + (size_t)s2 * DOUT + 2 * lane);
        float2 v3 = *(const float2*)(g_bufU + (size_t)s3 * DOUT + 2 * lane);
        acc.x += v0.x + v1.x + v2.x + v3.x;
        acc.y += v0.y + v1.y + v2.y + v3.y;
    }
    for (; j < deg; j++) {
        int s = __ldg(g_srcs + start + j);
        float2 u = *(const float2*)(g_bufU + (size_t)s * DOUT + 2 * lane);
        acc.x += u.x; acc.y += u.y;
    }
    float2 c = *(const float2*)(g_c + 2 * lane);
    float2 o = make_float2(fmaf(di, acc.x, c.x), fmaf(di, acc.y, c.y));
    *(float2*)(out + (size_t)v * DOUT + 2 * lane) = o;
}

extern "C" void kernel_launch(void* const* d_in, const int* in_sizes, int n_in,
                              void* d_out, int out_size)
{
    const float* x    = (const float*)d_in[0];
    const int*   ei   = (const int*)  d_in[1];
    const float* W1   = (const float*)d_in[2];
    const float* b1   = (const float*)d_in[3];
    const float* W2   = (const float*)d_in[4];
    const float* b2   = (const float*)d_in[5];
    const float* Wout = (const float*)d_in[6];
    const float* bout = (const float*)d_in[7];
    const int* src = ei;
    const int* dst = ei + NE;
    float* out = (float*)d_out;

    const int SMEM_GEMM  = D * D * 4;       // 64 KB
    const int SMEM_SMALL = D * DOUT * 4;    // 20 KB

    cudaFuncSetAttribute(k_gemm, cudaFuncAttributeMaxDynamicSharedMemorySize, SMEM_GEMM);

    const int GEMM_GRID   = (NGROUP + 7) / 8;
    const int GATHER_GRID = (NN * 32 + 255) / 256;

    // ---- CSR build + weight folding ----
    k_zero<<<(NN + 255) / 256, 256>>>();
    k_hist<<<(NE + 255) / 256, 256>>>(dst);
    k_fold<<<(D * DOUT + DOUT + 255) / 256, 256>>>(W2, Wout, b2, bout);
    k_scan1<<<NSCANB, SCAN_B>>>();
    k_scan2<<<1, 256>>>();
    k_finalize<<<(NN + 255) / 256, 256>>>();
    k_scatter<<<(NE + 255) / 256, 256>>>(src, dst);

    // ---- layer 1 ----
    k_gemm<<<GEMM_GRID, 256, SMEM_GEMM>>>(x, W1);
    k_gather<<<GATHER_GRID, 256>>>();

    // ---- layer 2 folded with output layer ----
    k_small<<<GEMM_GRID, 256, SMEM_SMALL>>>(b1);
    k_gather2<<<GATHER_GRID, 256>>>(out);
}